// round 9
// baseline (speedup 1.0000x reference)
#include <cuda_runtime.h>
#include <math_constants.h>

#define BB 64
#define NN 64
#define TT 100
#define CH 10                      // t-slices per block
#define NCHUNK (TT / CH)           // 10, exact

// Partials: [chunk][n][b]  (164 KB, L2-resident)
static __device__ float g_partial[NCHUNK * NN * BB];

__global__ __launch_bounds__(CH * 32) void social_main_kernel(
    const float* __restrict__ x,
    const float* __restrict__ wfa,
    const int*   __restrict__ rand_idx,
    const int*   __restrict__ drop_mask)
{
    const int n     = blockIdx.x;             // 0..63
    const int chunk = blockIdx.y;             // 0..9
    const int tsub  = threadIdx.x >> 5;       // 0..9 (one warp per t-slice)
    const int lane  = threadIdx.x & 31;
    const int t     = chunk * CH + tsub;      // always < 100
    const int b1    = lane;                   // two targets per thread
    const int b2    = lane + 32;

    __shared__ float4 s[CH][BB];              // 10 KB
    __shared__ float  red[CH][BB];            // 2.5 KB

    // Transforms for both targets (wfa L1-hot: 64 rows reused by all blocks)
    const float* w1 = wfa + b1 * 9;
    const float* w2 = wfa + b2 * 9;

    // positions x[b, n, t, 0:2] (8B-aligned float2)
    const float2 q1 = *(const float2*)(x + (((size_t)(b1 * NN + n)) * TT + t) * 6);
    const float2 q2 = *(const float2*)(x + (((size_t)(b2 * NN + n)) * TT + t) * 6);

    const float gx1 = fmaf(w1[0], q1.x, w1[1] * q1.y) + w1[2];
    const float gy1 = fmaf(w1[3], q1.x, w1[4] * q1.y) + w1[5];
    const float sq1 = fmaf(gx1, gx1, gy1 * gy1);
    const float gx2 = fmaf(w2[0], q2.x, w2[1] * q2.y) + w2[2];
    const float gy2 = fmaf(w2[3], q2.x, w2[4] * q2.y) + w2[5];
    const float sq2 = fmaf(gx2, gx2, gy2 * gy2);

    s[tsub][b1] = make_float4(gx1, gy1, sq1, 0.0f);
    s[tsub][b2] = make_float4(gx2, gy2, sq2, 0.0f);
    __syncthreads();

    // Dense broadcast scan, one LDS.128 per candidate feeding BOTH targets.
    // Key = clamp(sq_b + sq_c - 2*dot, 1e-12) > 0 -> float-bit order ==
    // numeric order; pack c into the 6 low mantissa bits; unsigned-min argmin
    // (low-bit index = first-occurrence tie-break, matching jnp.argmin).
    // Diagonal: for candidate c, only one target can match (c<32 -> b1,
    // c>=32 -> b2), resolved at compile time by the unroll.
    const float m2x1 = -2.0f * gx1, m2y1 = -2.0f * gy1;
    const float m2x2 = -2.0f * gx2, m2y2 = -2.0f * gy2;

    unsigned ua[4] = {0xFFFFFFFFu, 0xFFFFFFFFu, 0xFFFFFFFFu, 0xFFFFFFFFu};
    unsigned ubv[4] = {0xFFFFFFFFu, 0xFFFFFFFFu, 0xFFFFFFFFu, 0xFFFFFFFFu};
    #pragma unroll
    for (int c = 0; c < BB; ++c) {
        const float4 p = s[tsub][c];
        float k1 = fmaf(p.x, m2x1, fmaf(p.y, m2y1, p.z)) + sq1;
        float k2 = fmaf(p.x, m2x2, fmaf(p.y, m2y2, p.z)) + sq2;
        k1 = fmaxf(k1, 1e-12f);
        k2 = fmaxf(k2, 1e-12f);
        unsigned uk1 = (__float_as_uint(k1) & 0xFFFFFFC0u) | (unsigned)c;
        unsigned uk2 = (__float_as_uint(k2) & 0xFFFFFFC0u) | (unsigned)c;
        if (c < 32) { if (lane == c)      uk1 = 0xFFFFFFFFu; }
        else        { if (lane == c - 32) uk2 = 0xFFFFFFFFu; }
        ua[c & 3]  = min(ua[c & 3],  uk1);
        ubv[c & 3] = min(ubv[c & 3], uk2);
    }
    const int cmin1 = (int)(min(min(ua[0], ua[1]),  min(ua[2], ua[3]))  & 63u);
    const int cmin2 = (int)(min(min(ubv[0], ubv[1]), min(ubv[2], ubv[3])) & 63u);

    // Neighbor pick + loss for both targets (coalesced control loads)
    const int rowBase = (t * NN + n) * BB;
    const int ri1 = rand_idx[rowBase + b1];
    const int ri2 = rand_idx[rowBase + b2];
    const int dr1 = drop_mask[rowBase + b1];
    const int dr2 = drop_mask[rowBase + b2];

    const int nb1 = dr1 ? (ri1 + (ri1 >= b1 ? 1 : 0)) : cmin1;
    const int nb2 = dr2 ? (ri2 + (ri2 >= b2 ? 1 : 0)) : cmin2;

    const float4 p1 = s[tsub][nb1];
    const float4 p2 = s[tsub][nb2];
    const float d2a = (sq1 + p1.z) - 2.0f * fmaf(gx1, p1.x, gy1 * p1.y);
    const float d2b = (sq2 + p2.z) - 2.0f * fmaf(gx2, p2.x, gy2 * p2.y);
    const float df1 = sqrtf(fmaxf(d2a, 1e-12f)) - 1.5f;
    const float df2 = sqrtf(fmaxf(d2b, 1e-12f)) - 1.5f;

    red[tsub][b1] = df1 * df1;
    red[tsub][b2] = df2 * df2;
    __syncthreads();

    // Sum over the CH t-slices, store coalesced partial for this (chunk, n)
    if (threadIdx.x < BB) {
        const int b = threadIdx.x;
        float acc = 0.0f;
        #pragma unroll
        for (int j = 0; j < CH; ++j) acc += red[j][b];
        g_partial[(chunk * NN + n) * BB + b] = acc;
    }
}

__global__ __launch_bounds__(256) void social_reduce_kernel(float* __restrict__ out)
{
    const int q = blockIdx.x * blockDim.x + threadIdx.x;  // 0..4095
    const int b = q & 63;                                 // consecutive q -> consecutive b
    const int n = q >> 6;

    float acc = 0.0f;
    #pragma unroll
    for (int k = 0; k < NCHUNK; ++k)                      // coalesced, L2-hot, MLP=10
        acc += g_partial[(k * NN + n) * BB + b];

    out[b * NN + n] = acc * (1.0f / (float)TT);
}

extern "C" void kernel_launch(void* const* d_in, const int* in_sizes, int n_in,
                              void* d_out, int out_size)
{
    const float* x    = (const float*)d_in[0];
    const float* wfa  = (const float*)d_in[1];
    const int*   ridx = (const int*)d_in[2];
    const int*   mask = (const int*)d_in[3];
    float*       out  = (float*)d_out;

    dim3 grid(NN, NCHUNK);
    social_main_kernel<<<grid, CH * 32>>>(x, wfa, ridx, mask);
    social_reduce_kernel<<<(NN * BB) / 256, 256>>>(out);
}

// round 10
// speedup vs baseline: 2.1899x; 2.1899x over previous
#include <cuda_runtime.h>
#include <math_constants.h>

#define BB 64
#define NN 64
#define TT 100
#define CH 4                       // t-slices per block
#define NCHUNK (TT / CH)           // 25

// Partials: [chunk][n][b] (400 KB, L2-resident)
static __device__ float g_partial[NCHUNK * NN * BB];

__global__ __launch_bounds__(CH * BB) void social_main_kernel(
    const float* __restrict__ x,
    const float* __restrict__ wfa,
    const int*   __restrict__ rand_idx,
    const int*   __restrict__ drop_mask)
{
    const int n     = blockIdx.x;            // 0..63
    const int chunk = blockIdx.y;            // 0..24
    const int tsub  = threadIdx.x >> 6;      // 0..3
    const int b     = threadIdx.x & 63;      // 0..63
    const int lane  = threadIdx.x & 31;
    const int base  = b & 32;                // which b-half this warp owns
    const int t     = chunk * CH + tsub;     // < 100 always

    __shared__ float4 s[CH][BB];             // 4 KB
    __shared__ float  red[CH * BB];          // 1 KB

    // Per-batch transform R, trans (L1-hot)
    const float* w = wfa + b * 9;
    const float r00 = w[0], r01 = w[1], tx = w[2];
    const float r10 = w[3], r11 = w[4], ty = w[5];

    // pos = x[b, n, t, 0:2]
    const float2 p2 = *(const float2*)(x + (((size_t)(b * NN + n)) * TT + t) * 6);

    const float gx = fmaf(r00, p2.x, r01 * p2.y) + tx;
    const float gy = fmaf(r10, p2.x, r11 * p2.y) + ty;
    const float sq = fmaf(gx, gx, gy * gy);

    s[tsub][b] = make_float4(gx, gy, sq, 0.0f);

    // Control loads (coalesced in b), issued before the barrier
    const int idx  = (t * NN + n) * BB + b;  // row = t*N + n, col = b
    const int ri   = rand_idx[idx];
    const int drop = drop_mask[idx];
    __syncthreads();

    // My two candidates (c = lane, c = lane+32), premultiplied by -2.
    const float4 caf = s[tsub][lane];
    const float4 cbf = s[tsub][lane + 32];
    const float ca2x = -2.0f * caf.x, ca2y = -2.0f * caf.y, caz = caf.z;
    const float cb2x = -2.0f * cbf.x, cb2y = -2.0f * cbf.y, cbz = cbf.z;

    // Compacted argmin: only lanes with drop==0 (~20%) need it.
    // For each needy target tb, all 32 lanes evaluate their 2 candidates from
    // registers and REDUX-min the packed (key & ~63) | c. Keys positive after
    // the 1e-12 clamp -> unsigned order == float order; low-bit index breaks
    // ties toward smaller c (jnp.argmin first-occurrence). REDUXes across
    // iterations are independent -> pipelined.
    unsigned int my_cmin = 0;
    const unsigned need = __ballot_sync(0xffffffffu, drop == 0);
    for (unsigned m = need; m; m &= m - 1u) {
        const int tb = __ffs(m) - 1;            // target lane
        const float4 tg = s[tsub][base | tb];   // broadcast LDS

        float k1 = fmaf(tg.x, ca2x, fmaf(tg.y, ca2y, caz)) + tg.z;
        float k2 = fmaf(tg.x, cb2x, fmaf(tg.y, cb2y, cbz)) + tg.z;
        k1 = fmaxf(k1, 1e-12f);
        k2 = fmaxf(k2, 1e-12f);
        unsigned uk1 = (__float_as_uint(k1) & 0xFFFFFFC0u) | (unsigned)lane;
        unsigned uk2 = (__float_as_uint(k2) & 0xFFFFFFC0u) | (unsigned)(lane + 32);

        // Diagonal: candidate c == target b sits at lane==tb, in the half
        // selected by base.
        if (lane == tb) { if (base) uk2 = 0xFFFFFFFFu; else uk1 = 0xFFFFFFFFu; }

        const unsigned best = __reduce_min_sync(0xffffffffu, min(uk1, uk2));
        if (tb == lane) my_cmin = best & 63u;
    }

    const int rnb = ri + (ri >= b ? 1 : 0);
    const int nb  = drop ? rnb : (int)my_cmin;

    const float4 p  = s[tsub][nb];
    const float  d2 = (sq + p.z) - 2.0f * fmaf(gx, p.x, gy * p.y);
    const float  nd = sqrtf(fmaxf(d2, 1e-12f));
    const float  df = nd - 1.5f;

    red[tsub * BB + b] = df * df;
    __syncthreads();

    if (tsub == 0) {
        const float acc = red[b] + red[BB + b] + red[2 * BB + b] + red[3 * BB + b];
        g_partial[(chunk * NN + n) * BB + b] = acc;   // coalesced in b
    }
}

__global__ __launch_bounds__(BB) void social_reduce_kernel(float* __restrict__ out)
{
    const int n = blockIdx.x;                 // 0..63
    const int b = threadIdx.x;                // 0..63

    float acc = 0.0f;
    #pragma unroll
    for (int k = 0; k < NCHUNK; ++k)          // coalesced in b, MLP=25, L2-hot
        acc += g_partial[(k * NN + n) * BB + b];

    out[b * NN + n] = acc * (1.0f / (float)TT);
}

extern "C" void kernel_launch(void* const* d_in, const int* in_sizes, int n_in,
                              void* d_out, int out_size)
{
    const float* x    = (const float*)d_in[0];
    const float* wfa  = (const float*)d_in[1];
    const int*   ridx = (const int*)d_in[2];
    const int*   mask = (const int*)d_in[3];
    float*       out  = (float*)d_out;

    dim3 grid(NN, NCHUNK);
    social_main_kernel<<<grid, CH * BB>>>(x, wfa, ridx, mask);
    social_reduce_kernel<<<NN, BB>>>(out);
}

// round 12
// speedup vs baseline: 2.2383x; 1.0221x over previous
#include <cuda_runtime.h>
#include <math_constants.h>

#define BB 64
#define NN 64
#define TT 100
#define CH 10                      // t-slices per block
#define NCHUNK (TT / CH)           // 10, exact
#define NTHR (CH * BB)             // 640

// Partials: [chunk][n][b] (160 KB, L2-resident)
static __device__ float g_partial[NCHUNK * NN * BB];

__global__ __launch_bounds__(NTHR) void social_main_kernel(
    const float* __restrict__ x,
    const float* __restrict__ wfa,
    const int*   __restrict__ rand_idx,
    const int*   __restrict__ drop_mask)
{
    const int n     = blockIdx.x;            // 0..63
    const int chunk = blockIdx.y;            // 0..9
    const int tid   = threadIdx.x;
    const int tsub  = tid >> 6;              // 0..9
    const int b     = tid & 63;              // 0..63
    const int lane  = tid & 31;
    const int base  = b & 32;                // b-half this warp owns
    const int t     = chunk * CH + tsub;     // < 100 always

    __shared__ float2 sx[BB][3 * CH];        // staged x: 64 rows x 30 float2 (15.4 KB)
    __shared__ float4 s[CH][BB];             // 10 KB
    __shared__ float  red[CH][BB];           // 2.5 KB

    // Stage x cooperatively: row b needs floats [base + 0 .. 60) where
    // base = ((b*NN+n)*TT + chunk*CH)*6  -> 30 aligned float2 per row.
    // Consecutive threads load consecutive float2 within a row -> ~3
    // sectors/warp instead of 32.
    const float2* x2 = (const float2*)x;
    #pragma unroll
    for (int i = tid; i < BB * 3 * CH; i += NTHR) {
        const int bb = i / (3 * CH);
        const int j  = i - bb * (3 * CH);
        sx[bb][j] = x2[((size_t)(bb * NN + n) * TT + chunk * CH) * 3 + j];
    }

    // Per-batch transform R, trans (L1-hot)
    const float* w = wfa + b * 9;
    const float r00 = w[0], r01 = w[1], tx = w[2];
    const float r10 = w[3], r11 = w[4], ty = w[5];

    // Control loads (coalesced in b)
    const int idx  = (t * NN + n) * BB + b;  // row = t*N + n, col = b
    const int ri   = rand_idx[idx];
    const int drop = drop_mask[idx];
    __syncthreads();

    // (px, py) = floats at t-offset tsub*6, tsub*6+1 -> float2 index tsub*3
    const float2 p2 = sx[b][tsub * 3];

    const float gx = fmaf(r00, p2.x, r01 * p2.y) + tx;
    const float gy = fmaf(r10, p2.x, r11 * p2.y) + ty;
    const float sq = fmaf(gx, gx, gy * gy);

    s[tsub][b] = make_float4(gx, gy, sq, 0.0f);
    __syncthreads();

    // My two candidates (c = lane, c = lane+32), premultiplied by -2.
    const float4 caf = s[tsub][lane];
    const float4 cbf = s[tsub][lane + 32];
    const float ca2x = -2.0f * caf.x, ca2y = -2.0f * caf.y, caz = caf.z;
    const float cb2x = -2.0f * cbf.x, cb2y = -2.0f * cbf.y, cbz = cbf.z;

    // Compacted argmin (proven in R10): only drop==0 lanes (~20%) need it.
    // Packed key (key & ~63) | c, REDUX.MIN per needy target; low-bit index
    // breaks ties toward smaller c (jnp.argmin first-occurrence).
    unsigned int my_cmin = 0;
    const unsigned need = __ballot_sync(0xffffffffu, drop == 0);
    for (unsigned m = need; m; m &= m - 1u) {
        const int tb = __ffs(m) - 1;            // target lane
        const float4 tg = s[tsub][base | tb];   // broadcast LDS

        float k1 = fmaf(tg.x, ca2x, fmaf(tg.y, ca2y, caz)) + tg.z;
        float k2 = fmaf(tg.x, cb2x, fmaf(tg.y, cb2y, cbz)) + tg.z;
        k1 = fmaxf(k1, 1e-12f);
        k2 = fmaxf(k2, 1e-12f);
        unsigned uk1 = (__float_as_uint(k1) & 0xFFFFFFC0u) | (unsigned)lane;
        unsigned uk2 = (__float_as_uint(k2) & 0xFFFFFFC0u) | (unsigned)(lane + 32);

        // Diagonal: candidate c == target b sits at lane==tb, half = base.
        if (lane == tb) { if (base) uk2 = 0xFFFFFFFFu; else uk1 = 0xFFFFFFFFu; }

        const unsigned best = __reduce_min_sync(0xffffffffu, min(uk1, uk2));
        if (tb == lane) my_cmin = best & 63u;
    }

    const int rnb = ri + (ri >= b ? 1 : 0);
    const int nb  = drop ? rnb : (int)my_cmin;

    const float4 p  = s[tsub][nb];
    const float  d2 = (sq + p.z) - 2.0f * fmaf(gx, p.x, gy * p.y);
    const float  nd = sqrtf(fmaxf(d2, 1e-12f));
    const float  df = nd - 1.5f;

    red[tsub][b] = df * df;
    __syncthreads();

    if (tsub == 0) {
        float acc = 0.0f;
        #pragma unroll
        for (int j = 0; j < CH; ++j) acc += red[j][b];
        g_partial[(chunk * NN + n) * BB + b] = acc;   // coalesced in b
    }
}

__global__ __launch_bounds__(128) void social_reduce_kernel(float* __restrict__ out)
{
    const int q = blockIdx.x * blockDim.x + threadIdx.x;  // 0..4095
    const int b = q & 63;                                 // consecutive q -> consecutive b
    const int n = q >> 6;

    float acc = 0.0f;
    #pragma unroll
    for (int k = 0; k < NCHUNK; ++k)                      // coalesced, MLP=10, L2-hot
        acc += g_partial[(k * NN + n) * BB + b];

    out[b * NN + n] = acc * (1.0f / (float)TT);
}

extern "C" void kernel_launch(void* const* d_in, const int* in_sizes, int n_in,
                              void* d_out, int out_size)
{
    const float* x    = (const float*)d_in[0];
    const float* wfa  = (const float*)d_in[1];
    const int*   ridx = (const int*)d_in[2];
    const int*   mask = (const int*)d_in[3];
    float*       out  = (float*)d_out;

    dim3 grid(NN, NCHUNK);
    social_main_kernel<<<grid, NTHR>>>(x, wfa, ridx, mask);
    social_reduce_kernel<<<(NN * BB) / 128, 128>>>(out);
}